// round 2
// baseline (speedup 1.0000x reference)
#include <cuda_runtime.h>

#define NT 8192
#define ND 2048
#define NE 16
#define CAP 512
#define FULLM 0xFFFFFFFFu

typedef unsigned long long u64;

__device__ float g_probs[NT * NE];   // softmax probs per token
__device__ u64   g_prefs[NT];        // packed expert-preference order (16 nibbles)

__device__ __forceinline__ u64 ffma2(u64 a, u64 b, u64 c) {
    u64 d;
    asm("fma.rn.f32x2 %0, %1, %2, %3;" : "=l"(d) : "l"(a), "l"(b), "l"(c));
    return d;
}

// =====================================================================
// Kernel 1: GEMV + softmax + preference packing.
// 4 warps/block, 4 tokens/warp, lanes split K. Packed f32x2 FMAs:
// each u64 acc holds (sum over x,z comps | sum over y,w comps).
// =====================================================================
__global__ void __launch_bounds__(128) gemv_kernel(const float* __restrict__ f,
                                                   const float* __restrict__ W,
                                                   const float* __restrict__ b) {
    const int lane = threadIdx.x & 31;
    const int wid  = threadIdx.x >> 5;
    const int t0   = (blockIdx.x * 4 + wid) * 4;

    const ulonglong2* F  = reinterpret_cast<const ulonglong2*>(f + (size_t)t0 * ND);
    const ulonglong2* Wv = reinterpret_cast<const ulonglong2*>(W);

    u64 acc[4][NE];
#pragma unroll
    for (int t = 0; t < 4; ++t)
#pragma unroll
        for (int e = 0; e < NE; ++e) acc[t][e] = 0ull;

#pragma unroll 2
    for (int i = 0; i < 16; ++i) {
        const int k = i * 32 + lane;                  // ulonglong2 (16B) index
        const ulonglong2 a0 = F[k];
        const ulonglong2 a1 = F[k + 512];
        const ulonglong2 a2 = F[k + 1024];
        const ulonglong2 a3 = F[k + 1536];
#pragma unroll
        for (int e = 0; e < NE; ++e) {
            const ulonglong2 w = Wv[e * 512 + k];
            acc[0][e] = ffma2(a0.x, w.x, acc[0][e]);
            acc[0][e] = ffma2(a0.y, w.y, acc[0][e]);
            acc[1][e] = ffma2(a1.x, w.x, acc[1][e]);
            acc[1][e] = ffma2(a1.y, w.y, acc[1][e]);
            acc[2][e] = ffma2(a2.x, w.x, acc[2][e]);
            acc[2][e] = ffma2(a2.y, w.y, acc[2][e]);
            acc[3][e] = ffma2(a3.x, w.x, acc[3][e]);
            acc[3][e] = ffma2(a3.y, w.y, acc[3][e]);
        }
    }

    // reduce: fold packed halves, butterfly across lanes; lane t keeps token t
    float aff[NE];
#pragma unroll
    for (int t = 0; t < 4; ++t) {
#pragma unroll
        for (int e = 0; e < NE; ++e) {
            float sv = __uint_as_float((unsigned)acc[t][e]) +
                       __uint_as_float((unsigned)(acc[t][e] >> 32));
#pragma unroll
            for (int o = 16; o; o >>= 1) sv += __shfl_xor_sync(FULLM, sv, o);
            if (lane == t) aff[e] = sv;
        }
    }

    if (lane < 4) {
        const int t = t0 + lane;
#pragma unroll
        for (int e = 0; e < NE; ++e) aff[e] += __ldg(b + e);

        // softmax
        float m = aff[0];
#pragma unroll
        for (int e = 1; e < NE; ++e) m = fmaxf(m, aff[e]);
        float p[NE]; float s = 0.f;
#pragma unroll
        for (int e = 0; e < NE; ++e) { p[e] = expf(aff[e] - m); s += p[e]; }
        const float inv = 1.f / s;
#pragma unroll
        for (int e = 0; e < NE; ++e) g_probs[t * NE + e] = p[e] * inv;

        // preference order: descending score, tie -> lower expert index
        u64 key[NE];
#pragma unroll
        for (int e = 0; e < NE; ++e) {
            unsigned u = __float_as_uint(aff[e]);
            u = (u & 0x80000000u) ? ~u : (u | 0x80000000u);
            key[e] = (1ull << 40) | ((u64)u << 4) | (u64)(NE - 1 - e);
        }
        unsigned used = 0;
        u64 pref = 0;
#pragma unroll
        for (int i = 0; i < NE; ++i) {
            int best = 0; u64 bk = 0;
#pragma unroll
            for (int e = 0; e < NE; ++e) {
                const bool take = !((used >> e) & 1u) && key[e] > bk;
                bk   = take ? key[e] : bk;
                best = take ? e : best;
            }
            used |= 1u << best;
            pref |= ((u64)best) << (4 * i);
        }
        g_prefs[t] = pref;
    }
}

// =====================================================================
// Kernel 2: phased balanced assignment, register-resident.
// Warp w owns tokens [w*256, w*256+256); lane l, step j -> t = w*256+j*32+l.
// Per phase: re-derive only tokens whose choice expert just saturated,
// count via packed u16x16 regs + warp butterfly + 32-warp scan, find cut
// via ballots, advance.
// =====================================================================
__global__ void __launch_bounds__(1024) assign_kernel(float* __restrict__ out) {
    __shared__ u64 s_w[32][4];
    __shared__ int s_fin[NE];
    __shared__ int s_active, s_start, s_cut, s_estar;

    const int tid  = threadIdx.x;
    const int lane = tid & 31;
    const int wid  = tid >> 5;
    const int base = wid * 256;
    const unsigned ltm = (1u << lane) - 1u;

    u64 pref[8];
    int ch[8];
#pragma unroll
    for (int j = 0; j < 8; ++j) pref[j] = g_prefs[base + j * 32 + lane];
#pragma unroll
    for (int j = 0; j < 8; ++j) ch[j] = 0;

    if (tid < NE) s_fin[tid] = 0;
    if (tid == 0) { s_active = 0xFFFF; s_start = 0; s_estar = -1; s_cut = 0x7FFFFFFF; }
    __syncthreads();

    for (int phase = 0; phase <= NE; ++phase) {
        const int s = s_start;
        if (s >= NT) break;
        const int active = s_active;
        const int estar  = s_estar;

        // derive choices + packed per-expert counts over active region
        u64 c0 = 0, c1 = 0, c2 = 0, c3 = 0;
#pragma unroll
        for (int j = 0; j < 8; ++j) {
            const int t = base + j * 32 + lane;
            if (t >= s) {
                if (estar < 0 || ch[j] == estar) {
                    u64 p = pref[j];
                    int c = (int)(p & 15);
                    while (!((active >> c) & 1)) { p >>= 4; c = (int)(p & 15); }
                    ch[j] = c;
                }
                const int c = ch[j];
                const u64 inc = 1ull << ((c & 3) << 4);
                if      ((c >> 2) == 0) c0 += inc;
                else if ((c >> 2) == 1) c1 += inc;
                else if ((c >> 2) == 2) c2 += inc;
                else                    c3 += inc;
            }
        }
        // warp totals
#pragma unroll
        for (int o = 16; o; o >>= 1) {
            c0 += __shfl_xor_sync(FULLM, c0, o);
            c1 += __shfl_xor_sync(FULLM, c1, o);
            c2 += __shfl_xor_sync(FULLM, c2, o);
            c3 += __shfl_xor_sync(FULLM, c3, o);
        }
        if (lane == 0) { s_w[wid][0] = c0; s_w[wid][1] = c1; s_w[wid][2] = c2; s_w[wid][3] = c3; }
        __syncthreads();
        // cross-warp exclusive scan (warp 0)
        if (wid == 0) {
            u64 v0 = s_w[lane][0], v1 = s_w[lane][1], v2 = s_w[lane][2], v3 = s_w[lane][3];
            u64 i0 = v0, i1 = v1, i2 = v2, i3 = v3;
#pragma unroll
            for (int o = 1; o < 32; o <<= 1) {
                u64 u0 = __shfl_up_sync(FULLM, i0, o), u1 = __shfl_up_sync(FULLM, i1, o);
                u64 u2 = __shfl_up_sync(FULLM, i2, o), u3 = __shfl_up_sync(FULLM, i3, o);
                if (lane >= o) { i0 += u0; i1 += u1; i2 += u2; i3 += u3; }
            }
            s_w[lane][0] = i0 - v0; s_w[lane][1] = i1 - v1;
            s_w[lane][2] = i2 - v2; s_w[lane][3] = i3 - v3;
        }
        __syncthreads();
        const u64 p0 = s_w[wid][0], p1 = s_w[wid][1], p2 = s_w[wid][2], p3 = s_w[wid][3];

        // find earliest saturation (atomicMin over (pos<<4)|e)
#pragma unroll
        for (int e = 0; e < NE; ++e) {
            if (!((active >> e) & 1)) continue;
            const u64 pw = (e >> 2) == 0 ? p0 : (e >> 2) == 1 ? p1 : (e >> 2) == 2 ? p2 : p3;
            const u64 cw = (e >> 2) == 0 ? c0 : (e >> 2) == 1 ? c1 : (e >> 2) == 2 ? c2 : c3;
            const int pe   = (int)((pw >> ((e & 3) << 4)) & 0xFFFF);
            const int ce   = (int)((cw >> ((e & 3) << 4)) & 0xFFFF);
            const int need = CAP - s_fin[e];
            if (pe < need && pe + ce >= need) {
                const int rem = need - pe;
                int cum = 0, pos = -1;
#pragma unroll
                for (int j = 0; j < 8; ++j) {
                    const unsigned bal = __ballot_sync(FULLM,
                        (ch[j] == e) && (base + j * 32 + lane >= s));
                    const int cc = __popc(bal);
                    if (pos < 0 && cum + cc >= rem) {
                        int k = rem - cum;
                        unsigned mm = bal;
                        while (--k) mm &= mm - 1;
                        pos = base + j * 32 + (__ffs(mm) - 1);
                    }
                    cum += cc;
                }
                if (lane == 0) atomicMin(&s_cut, (pos << 4) | e);
            }
        }
        __syncthreads();
        const int mv = s_cut;
        if (mv == 0x7FFFFFFF) {          // cannot happen (caps == tokens), safety
            if (tid == 0) s_start = NT;
            __syncthreads();
            continue;
        }
        const int pstar = mv >> 4, es = mv & 15;

        // finalized-count update: counts of tokens in [s, pstar]
        u64 d0 = 0, d1 = 0, d2 = 0, d3 = 0;
#pragma unroll
        for (int j = 0; j < 8; ++j) {
            const int t = base + j * 32 + lane;
            if (t >= s && t <= pstar) {
                const int c = ch[j];
                const u64 inc = 1ull << ((c & 3) << 4);
                if      ((c >> 2) == 0) d0 += inc;
                else if ((c >> 2) == 1) d1 += inc;
                else if ((c >> 2) == 2) d2 += inc;
                else                    d3 += inc;
            }
        }
#pragma unroll
        for (int o = 16; o; o >>= 1) {
            d0 += __shfl_xor_sync(FULLM, d0, o);
            d1 += __shfl_xor_sync(FULLM, d1, o);
            d2 += __shfl_xor_sync(FULLM, d2, o);
            d3 += __shfl_xor_sync(FULLM, d3, o);
        }
        if (lane == 0) { s_w[wid][0] = d0; s_w[wid][1] = d1; s_w[wid][2] = d2; s_w[wid][3] = d3; }
        __syncthreads();
        if (wid == 0) {
            u64 t0_ = s_w[lane][0], t1_ = s_w[lane][1], t2_ = s_w[lane][2], t3_ = s_w[lane][3];
#pragma unroll
            for (int o = 16; o; o >>= 1) {
                t0_ += __shfl_xor_sync(FULLM, t0_, o);
                t1_ += __shfl_xor_sync(FULLM, t1_, o);
                t2_ += __shfl_xor_sync(FULLM, t2_, o);
                t3_ += __shfl_xor_sync(FULLM, t3_, o);
            }
#pragma unroll
            for (int e = 0; e < NE; ++e) {
                if (lane == e) {
                    const u64 tv = (e >> 2) == 0 ? t0_ : (e >> 2) == 1 ? t1_
                                 : (e >> 2) == 2 ? t2_ : t3_;
                    s_fin[e] += (int)((tv >> ((e & 3) << 4)) & 0xFFFF);
                }
            }
            if (lane == 0) {
                s_active = active & ~(1 << es);
                s_start  = pstar + 1;
                s_estar  = es;
                s_cut    = 0x7FFFFFFF;
            }
        }
        __syncthreads();
    }

    // ---------------- stable counting sort + gather ----------------
    {
        u64 c0 = 0, c1 = 0, c2 = 0, c3 = 0;
#pragma unroll
        for (int j = 0; j < 8; ++j) {
            const int c = ch[j];
            const u64 inc = 1ull << ((c & 3) << 4);
            if      ((c >> 2) == 0) c0 += inc;
            else if ((c >> 2) == 1) c1 += inc;
            else if ((c >> 2) == 2) c2 += inc;
            else                    c3 += inc;
        }
#pragma unroll
        for (int o = 16; o; o >>= 1) {
            c0 += __shfl_xor_sync(FULLM, c0, o);
            c1 += __shfl_xor_sync(FULLM, c1, o);
            c2 += __shfl_xor_sync(FULLM, c2, o);
            c3 += __shfl_xor_sync(FULLM, c3, o);
        }
        if (lane == 0) { s_w[wid][0] = c0; s_w[wid][1] = c1; s_w[wid][2] = c2; s_w[wid][3] = c3; }
        __syncthreads();
        if (wid == 0) {
            u64 v0 = s_w[lane][0], v1 = s_w[lane][1], v2 = s_w[lane][2], v3 = s_w[lane][3];
            u64 i0 = v0, i1 = v1, i2 = v2, i3 = v3;
#pragma unroll
            for (int o = 1; o < 32; o <<= 1) {
                u64 u0 = __shfl_up_sync(FULLM, i0, o), u1 = __shfl_up_sync(FULLM, i1, o);
                u64 u2 = __shfl_up_sync(FULLM, i2, o), u3 = __shfl_up_sync(FULLM, i3, o);
                if (lane >= o) { i0 += u0; i1 += u1; i2 += u2; i3 += u3; }
            }
            s_w[lane][0] = i0 - v0; s_w[lane][1] = i1 - v1;
            s_w[lane][2] = i2 - v2; s_w[lane][3] = i3 - v3;
        }
        __syncthreads();
        const u64 p0 = s_w[wid][0], p1 = s_w[wid][1], p2 = s_w[wid][2], p3 = s_w[wid][3];

        u64 r0 = 0, r1 = 0, r2 = 0, r3 = 0;   // counts over earlier j within warp
#pragma unroll
        for (int j = 0; j < 8; ++j) {
            const int myE = ch[j];
            int rank = 0;
#pragma unroll
            for (int e = 0; e < NE; ++e) {
                const unsigned bal = __ballot_sync(FULLM, myE == e);
                if (myE == e) {
                    const u64 pw = (e >> 2) == 0 ? p0 : (e >> 2) == 1 ? p1
                                 : (e >> 2) == 2 ? p2 : p3;
                    const u64 rw = (e >> 2) == 0 ? r0 : (e >> 2) == 1 ? r1
                                 : (e >> 2) == 2 ? r2 : r3;
                    rank = (int)((pw >> ((e & 3) << 4)) & 0xFFFF)
                         + (int)((rw >> ((e & 3) << 4)) & 0xFFFF)
                         + __popc(bal & ltm);
                }
                const u64 inc = (u64)__popc(bal) << ((e & 3) << 4);
                if      ((e >> 2) == 0) r0 += inc;
                else if ((e >> 2) == 1) r1 += inc;
                else if ((e >> 2) == 2) r2 += inc;
                else                    r3 += inc;
            }
            const int t = base + j * 32 + lane;
            out[myE * CAP + rank] = (float)t;
            out[NT + t] = g_probs[t * NE + myE];
        }
    }
}

// =====================================================================
extern "C" void kernel_launch(void* const* d_in, const int* in_sizes, int n_in,
                              void* d_out, int out_size) {
    const float* f = (const float*)d_in[0];   // features [8192, 2048] f32
    const float* W = (const float*)d_in[1];   // gate weight [16, 2048] f32
    const float* b = (const float*)d_in[2];   // bias [16] f32
    float* out = (float*)d_out;               // [8192] sort_by_expert ++ [8192] gathered

    gemv_kernel<<<NT / 16, 128>>>(f, W, b);
    assign_kernel<<<1, 1024>>>(out);
}

// round 3
// speedup vs baseline: 1.1027x; 1.1027x over previous
#include <cuda_runtime.h>

#define NT 8192
#define ND 2048
#define NE 16
#define CAP 512
#define FULLM 0xFFFFFFFFu

typedef unsigned long long u64;

__device__ float g_probs[NT * NE];   // softmax probs per token
__device__ u64   g_prefs[NT];        // packed expert-preference order (16 nibbles)

__device__ __forceinline__ u64 ffma2(u64 a, u64 b, u64 c) {
    u64 d;
    asm("fma.rn.f32x2 %0, %1, %2, %3;" : "=l"(d) : "l"(a), "l"(b), "l"(c));
    return d;
}

// =====================================================================
// Kernel 1: GEMV + softmax + preference packing (unchanged — ~8us,
// at the HBM floor for the 64MB feature read).
// =====================================================================
__global__ void __launch_bounds__(128) gemv_kernel(const float* __restrict__ f,
                                                   const float* __restrict__ W,
                                                   const float* __restrict__ b) {
    const int lane = threadIdx.x & 31;
    const int wid  = threadIdx.x >> 5;
    const int t0   = (blockIdx.x * 4 + wid) * 4;

    const ulonglong2* F  = reinterpret_cast<const ulonglong2*>(f + (size_t)t0 * ND);
    const ulonglong2* Wv = reinterpret_cast<const ulonglong2*>(W);

    u64 acc[4][NE];
#pragma unroll
    for (int t = 0; t < 4; ++t)
#pragma unroll
        for (int e = 0; e < NE; ++e) acc[t][e] = 0ull;

#pragma unroll 2
    for (int i = 0; i < 16; ++i) {
        const int k = i * 32 + lane;
        const ulonglong2 a0 = F[k];
        const ulonglong2 a1 = F[k + 512];
        const ulonglong2 a2 = F[k + 1024];
        const ulonglong2 a3 = F[k + 1536];
#pragma unroll
        for (int e = 0; e < NE; ++e) {
            const ulonglong2 w = Wv[e * 512 + k];
            acc[0][e] = ffma2(a0.x, w.x, acc[0][e]);
            acc[0][e] = ffma2(a0.y, w.y, acc[0][e]);
            acc[1][e] = ffma2(a1.x, w.x, acc[1][e]);
            acc[1][e] = ffma2(a1.y, w.y, acc[1][e]);
            acc[2][e] = ffma2(a2.x, w.x, acc[2][e]);
            acc[2][e] = ffma2(a2.y, w.y, acc[2][e]);
            acc[3][e] = ffma2(a3.x, w.x, acc[3][e]);
            acc[3][e] = ffma2(a3.y, w.y, acc[3][e]);
        }
    }

    float aff[NE];
#pragma unroll
    for (int t = 0; t < 4; ++t) {
#pragma unroll
        for (int e = 0; e < NE; ++e) {
            float sv = __uint_as_float((unsigned)acc[t][e]) +
                       __uint_as_float((unsigned)(acc[t][e] >> 32));
#pragma unroll
            for (int o = 16; o; o >>= 1) sv += __shfl_xor_sync(FULLM, sv, o);
            if (lane == t) aff[e] = sv;
        }
    }

    if (lane < 4) {
        const int t = t0 + lane;
#pragma unroll
        for (int e = 0; e < NE; ++e) aff[e] += __ldg(b + e);

        float m = aff[0];
#pragma unroll
        for (int e = 1; e < NE; ++e) m = fmaxf(m, aff[e]);
        float p[NE]; float s = 0.f;
#pragma unroll
        for (int e = 0; e < NE; ++e) { p[e] = expf(aff[e] - m); s += p[e]; }
        const float inv = 1.f / s;
#pragma unroll
        for (int e = 0; e < NE; ++e) g_probs[t * NE + e] = p[e] * inv;

        u64 key[NE];
#pragma unroll
        for (int e = 0; e < NE; ++e) {
            unsigned u = __float_as_uint(aff[e]);
            u = (u & 0x80000000u) ? ~u : (u | 0x80000000u);
            key[e] = (1ull << 40) | ((u64)u << 4) | (u64)(NE - 1 - e);
        }
        unsigned used = 0;
        u64 pref = 0;
#pragma unroll
        for (int i = 0; i < NE; ++i) {
            int best = 0; u64 bk = 0;
#pragma unroll
            for (int e = 0; e < NE; ++e) {
                const bool take = !((used >> e) & 1u) && key[e] > bk;
                bk   = take ? key[e] : bk;
                best = take ? e : best;
            }
            used |= 1u << best;
            pref |= ((u64)best) << (4 * i);
        }
        g_prefs[t] = pref;
    }
}

// =====================================================================
// Kernel 2: phased balanced assignment.
// prefs in SMEM; per-thread 8 choices packed as nibbles in ONE u32
// (no spills). Warp w owns tokens [w*256,(w+1)*256); t = base+j*32+lane.
// =====================================================================
#define SMEM_BYTES (NT * 8 + 32 * 4 * 8 + 256)

__global__ void __launch_bounds__(1024) assign_kernel(float* __restrict__ out) {
    extern __shared__ unsigned char smem[];
    u64* s_pref = (u64*)smem;                        // [NT]
    u64 (*s_w)[4] = (u64(*)[4])(smem + NT * 8);      // [32][4]
    int* s_int = (int*)(smem + NT * 8 + 32 * 4 * 8); // fin[16], active, start, cut, estar

    const int tid  = threadIdx.x;
    const int lane = tid & 31;
    const int wid  = tid >> 5;
    const int base = wid * 256;
    const unsigned ltm = (1u << lane) - 1u;

    for (int i = tid; i < NT; i += 1024) s_pref[i] = g_prefs[i];
    if (tid < NE) s_int[tid] = 0;                    // finalized count per expert
    if (tid == 0) { s_int[16] = 0xFFFF; s_int[17] = 0; s_int[18] = 0x7FFFFFFF; s_int[19] = -1; }
    __syncthreads();

    unsigned chpack = 0;                             // 8 nibble choices

    for (int phase = 0; phase <= NE; ++phase) {
        const int s = s_int[17];
        if (s >= NT) break;
        const int active = s_int[16];
        const int estar  = s_int[19];

        // derive/update choices + packed per-expert counts over [s, NT)
        u64 c0 = 0, c1 = 0, c2 = 0, c3 = 0;
#pragma unroll
        for (int j = 0; j < 8; ++j) {
            const int t = base + j * 32 + lane;
            if (t >= s) {
                int c = (int)((chpack >> (4 * j)) & 15u);
                if (estar < 0 || c == estar) {
                    u64 p = s_pref[t];
                    c = (int)(p & 15);
                    while (!((active >> c) & 1)) { p >>= 4; c = (int)(p & 15); }
                    chpack = (chpack & ~(15u << (4 * j))) | ((unsigned)c << (4 * j));
                }
                const u64 inc = 1ull << ((c & 3) << 4);
                if      ((c >> 2) == 0) c0 += inc;
                else if ((c >> 2) == 1) c1 += inc;
                else if ((c >> 2) == 2) c2 += inc;
                else                    c3 += inc;
            }
        }
#pragma unroll
        for (int o = 16; o; o >>= 1) {
            c0 += __shfl_xor_sync(FULLM, c0, o);
            c1 += __shfl_xor_sync(FULLM, c1, o);
            c2 += __shfl_xor_sync(FULLM, c2, o);
            c3 += __shfl_xor_sync(FULLM, c3, o);
        }
        if (lane == 0) { s_w[wid][0] = c0; s_w[wid][1] = c1; s_w[wid][2] = c2; s_w[wid][3] = c3; }
        __syncthreads();
        if (wid == 0) {                              // cross-warp exclusive scan
            u64 v0 = s_w[lane][0], v1 = s_w[lane][1], v2 = s_w[lane][2], v3 = s_w[lane][3];
            u64 i0 = v0, i1 = v1, i2 = v2, i3 = v3;
#pragma unroll
            for (int o = 1; o < 32; o <<= 1) {
                u64 u0 = __shfl_up_sync(FULLM, i0, o), u1 = __shfl_up_sync(FULLM, i1, o);
                u64 u2 = __shfl_up_sync(FULLM, i2, o), u3 = __shfl_up_sync(FULLM, i3, o);
                if (lane >= o) { i0 += u0; i1 += u1; i2 += u2; i3 += u3; }
            }
            s_w[lane][0] = i0 - v0; s_w[lane][1] = i1 - v1;
            s_w[lane][2] = i2 - v2; s_w[lane][3] = i3 - v3;
        }
        __syncthreads();
        const u64 p0 = s_w[wid][0], p1 = s_w[wid][1], p2 = s_w[wid][2], p3 = s_w[wid][3];

        // earliest saturation
#pragma unroll
        for (int e = 0; e < NE; ++e) {
            if (!((active >> e) & 1)) continue;
            const u64 pw = (e >> 2) == 0 ? p0 : (e >> 2) == 1 ? p1 : (e >> 2) == 2 ? p2 : p3;
            const u64 cw = (e >> 2) == 0 ? c0 : (e >> 2) == 1 ? c1 : (e >> 2) == 2 ? c2 : c3;
            const int pe   = (int)((pw >> ((e & 3) << 4)) & 0xFFFF);
            const int ce   = (int)((cw >> ((e & 3) << 4)) & 0xFFFF);
            const int need = CAP - s_int[e];
            if (pe < need && pe + ce >= need) {
                const int rem = need - pe;
                int cum = 0, pos = -1;
#pragma unroll
                for (int j = 0; j < 8; ++j) {
                    const int myc = (int)((chpack >> (4 * j)) & 15u);
                    const unsigned bal = __ballot_sync(FULLM,
                        (myc == e) && (base + j * 32 + lane >= s));
                    const int cc = __popc(bal);
                    if (pos < 0 && cum + cc >= rem) {
                        int k = rem - cum;
                        unsigned mm = bal;
                        while (--k) mm &= mm - 1;
                        pos = base + j * 32 + (__ffs(mm) - 1);
                    }
                    cum += cc;
                }
                if (lane == 0) atomicMin(&s_int[18], (pos << 4) | e);
            }
        }
        __syncthreads();
        const int mv = s_int[18];
        if (mv == 0x7FFFFFFF) {                      // safety; shouldn't happen
            if (tid == 0) s_int[17] = NT;
            __syncthreads();
            continue;
        }
        const int pstar = mv >> 4, es = mv & 15;

        // finalized counts of tokens in [s, pstar]
        u64 d0 = 0, d1 = 0, d2 = 0, d3 = 0;
#pragma unroll
        for (int j = 0; j < 8; ++j) {
            const int t = base + j * 32 + lane;
            if (t >= s && t <= pstar) {
                const int c = (int)((chpack >> (4 * j)) & 15u);
                const u64 inc = 1ull << ((c & 3) << 4);
                if      ((c >> 2) == 0) d0 += inc;
                else if ((c >> 2) == 1) d1 += inc;
                else if ((c >> 2) == 2) d2 += inc;
                else                    d3 += inc;
            }
        }
#pragma unroll
        for (int o = 16; o; o >>= 1) {
            d0 += __shfl_xor_sync(FULLM, d0, o);
            d1 += __shfl_xor_sync(FULLM, d1, o);
            d2 += __shfl_xor_sync(FULLM, d2, o);
            d3 += __shfl_xor_sync(FULLM, d3, o);
        }
        if (lane == 0) { s_w[wid][0] = d0; s_w[wid][1] = d1; s_w[wid][2] = d2; s_w[wid][3] = d3; }
        __syncthreads();
        if (wid == 0) {
            u64 t0_ = s_w[lane][0], t1_ = s_w[lane][1], t2_ = s_w[lane][2], t3_ = s_w[lane][3];
#pragma unroll
            for (int o = 16; o; o >>= 1) {
                t0_ += __shfl_xor_sync(FULLM, t0_, o);
                t1_ += __shfl_xor_sync(FULLM, t1_, o);
                t2_ += __shfl_xor_sync(FULLM, t2_, o);
                t3_ += __shfl_xor_sync(FULLM, t3_, o);
            }
            if (lane < NE) {
                const int e = lane;
                const u64 tv = (e >> 2) == 0 ? t0_ : (e >> 2) == 1 ? t1_
                             : (e >> 2) == 2 ? t2_ : t3_;
                s_int[e] += (int)((tv >> ((e & 3) << 4)) & 0xFFFF);
            }
            if (lane == 0) {
                s_int[16] = active & ~(1 << es);
                s_int[17] = pstar + 1;
                s_int[18] = 0x7FFFFFFF;
                s_int[19] = es;
            }
        }
        __syncthreads();
    }

    // ---------------- stable counting sort + gather ----------------
    {
        u64 c0 = 0, c1 = 0, c2 = 0, c3 = 0;
#pragma unroll
        for (int j = 0; j < 8; ++j) {
            const int c = (int)((chpack >> (4 * j)) & 15u);
            const u64 inc = 1ull << ((c & 3) << 4);
            if      ((c >> 2) == 0) c0 += inc;
            else if ((c >> 2) == 1) c1 += inc;
            else if ((c >> 2) == 2) c2 += inc;
            else                    c3 += inc;
        }
#pragma unroll
        for (int o = 16; o; o >>= 1) {
            c0 += __shfl_xor_sync(FULLM, c0, o);
            c1 += __shfl_xor_sync(FULLM, c1, o);
            c2 += __shfl_xor_sync(FULLM, c2, o);
            c3 += __shfl_xor_sync(FULLM, c3, o);
        }
        if (lane == 0) { s_w[wid][0] = c0; s_w[wid][1] = c1; s_w[wid][2] = c2; s_w[wid][3] = c3; }
        __syncthreads();
        if (wid == 0) {
            u64 v0 = s_w[lane][0], v1 = s_w[lane][1], v2 = s_w[lane][2], v3 = s_w[lane][3];
            u64 i0 = v0, i1 = v1, i2 = v2, i3 = v3;
#pragma unroll
            for (int o = 1; o < 32; o <<= 1) {
                u64 u0 = __shfl_up_sync(FULLM, i0, o), u1 = __shfl_up_sync(FULLM, i1, o);
                u64 u2 = __shfl_up_sync(FULLM, i2, o), u3 = __shfl_up_sync(FULLM, i3, o);
                if (lane >= o) { i0 += u0; i1 += u1; i2 += u2; i3 += u3; }
            }
            s_w[lane][0] = i0 - v0; s_w[lane][1] = i1 - v1;
            s_w[lane][2] = i2 - v2; s_w[lane][3] = i3 - v3;
        }
        __syncthreads();
        const u64 p0 = s_w[wid][0], p1 = s_w[wid][1], p2 = s_w[wid][2], p3 = s_w[wid][3];

        u64 r0 = 0, r1 = 0, r2 = 0, r3 = 0;          // earlier-j counts within warp
#pragma unroll
        for (int j = 0; j < 8; ++j) {
            const int myE = (int)((chpack >> (4 * j)) & 15u);
            int rank = 0;
#pragma unroll
            for (int e = 0; e < NE; ++e) {
                const unsigned bal = __ballot_sync(FULLM, myE == e);
                if (myE == e) {
                    const u64 pw = (e >> 2) == 0 ? p0 : (e >> 2) == 1 ? p1
                                 : (e >> 2) == 2 ? p2 : p3;
                    const u64 rw = (e >> 2) == 0 ? r0 : (e >> 2) == 1 ? r1
                                 : (e >> 2) == 2 ? r2 : r3;
                    rank = (int)((pw >> ((e & 3) << 4)) & 0xFFFF)
                         + (int)((rw >> ((e & 3) << 4)) & 0xFFFF)
                         + __popc(bal & ltm);
                }
                const u64 inc = (u64)__popc(bal) << ((e & 3) << 4);
                if      ((e >> 2) == 0) r0 += inc;
                else if ((e >> 2) == 1) r1 += inc;
                else if ((e >> 2) == 2) r2 += inc;
                else                    r3 += inc;
            }
            const int t = base + j * 32 + lane;
            out[myE * CAP + rank] = (float)t;
            out[NT + t] = g_probs[t * NE + myE];
        }
    }
}

// =====================================================================
extern "C" void kernel_launch(void* const* d_in, const int* in_sizes, int n_in,
                              void* d_out, int out_size) {
    const float* f = (const float*)d_in[0];   // features [8192, 2048] f32
    const float* W = (const float*)d_in[1];   // gate weight [16, 2048] f32
    const float* b = (const float*)d_in[2];   // bias [16] f32
    float* out = (float*)d_out;               // [8192] sort_by_expert ++ [8192] gathered

    gemv_kernel<<<NT / 16, 128>>>(f, W, b);

    cudaFuncSetAttribute(assign_kernel,
                         cudaFuncAttributeMaxDynamicSharedMemorySize, SMEM_BYTES);
    assign_kernel<<<1, 1024, SMEM_BYTES>>>(out);
}

// round 4
// speedup vs baseline: 2.4161x; 2.1910x over previous
#include <cuda_runtime.h>

#define NT 8192
#define ND 2048
#define NE 16
#define CAP 512
#define FULLM 0xFFFFFFFFu

typedef unsigned long long u64;

__device__ float g_probs[NT * NE];   // softmax probs per token
__device__ u64   g_prefs[NT];        // packed expert-preference order (16 nibbles)

__device__ __forceinline__ u64 ffma2(u64 a, u64 b, u64 c) {
    u64 d;
    asm("fma.rn.f32x2 %0, %1, %2, %3;" : "=l"(d) : "l"(a), "l"(b), "l"(c));
    return d;
}

// =====================================================================
// Kernel 1: GEMV + softmax + preference packing (unchanged; ~HBM floor)
// =====================================================================
__global__ void __launch_bounds__(128) gemv_kernel(const float* __restrict__ f,
                                                   const float* __restrict__ W,
                                                   const float* __restrict__ b) {
    const int lane = threadIdx.x & 31;
    const int wid  = threadIdx.x >> 5;
    const int t0   = (blockIdx.x * 4 + wid) * 4;

    const ulonglong2* F  = reinterpret_cast<const ulonglong2*>(f + (size_t)t0 * ND);
    const ulonglong2* Wv = reinterpret_cast<const ulonglong2*>(W);

    u64 acc[4][NE];
#pragma unroll
    for (int t = 0; t < 4; ++t)
#pragma unroll
        for (int e = 0; e < NE; ++e) acc[t][e] = 0ull;

#pragma unroll 2
    for (int i = 0; i < 16; ++i) {
        const int k = i * 32 + lane;
        const ulonglong2 a0 = F[k];
        const ulonglong2 a1 = F[k + 512];
        const ulonglong2 a2 = F[k + 1024];
        const ulonglong2 a3 = F[k + 1536];
#pragma unroll
        for (int e = 0; e < NE; ++e) {
            const ulonglong2 w = Wv[e * 512 + k];
            acc[0][e] = ffma2(a0.x, w.x, acc[0][e]);
            acc[0][e] = ffma2(a0.y, w.y, acc[0][e]);
            acc[1][e] = ffma2(a1.x, w.x, acc[1][e]);
            acc[1][e] = ffma2(a1.y, w.y, acc[1][e]);
            acc[2][e] = ffma2(a2.x, w.x, acc[2][e]);
            acc[2][e] = ffma2(a2.y, w.y, acc[2][e]);
            acc[3][e] = ffma2(a3.x, w.x, acc[3][e]);
            acc[3][e] = ffma2(a3.y, w.y, acc[3][e]);
        }
    }

    float aff[NE];
#pragma unroll
    for (int t = 0; t < 4; ++t) {
#pragma unroll
        for (int e = 0; e < NE; ++e) {
            float sv = __uint_as_float((unsigned)acc[t][e]) +
                       __uint_as_float((unsigned)(acc[t][e] >> 32));
#pragma unroll
            for (int o = 16; o; o >>= 1) sv += __shfl_xor_sync(FULLM, sv, o);
            if (lane == t) aff[e] = sv;
        }
    }

    if (lane < 4) {
        const int t = t0 + lane;
#pragma unroll
        for (int e = 0; e < NE; ++e) aff[e] += __ldg(b + e);

        float m = aff[0];
#pragma unroll
        for (int e = 1; e < NE; ++e) m = fmaxf(m, aff[e]);
        float p[NE]; float s = 0.f;
#pragma unroll
        for (int e = 0; e < NE; ++e) { p[e] = expf(aff[e] - m); s += p[e]; }
        const float inv = 1.f / s;
#pragma unroll
        for (int e = 0; e < NE; ++e) g_probs[t * NE + e] = p[e] * inv;

        u64 key[NE];
#pragma unroll
        for (int e = 0; e < NE; ++e) {
            unsigned u = __float_as_uint(aff[e]);
            u = (u & 0x80000000u) ? ~u : (u | 0x80000000u);
            key[e] = (1ull << 40) | ((u64)u << 4) | (u64)(NE - 1 - e);
        }
        unsigned used = 0;
        u64 pref = 0;
#pragma unroll
        for (int i = 0; i < NE; ++i) {
            int best = 0; u64 bk = 0;
#pragma unroll
            for (int e = 0; e < NE; ++e) {
                const bool take = !((used >> e) & 1u) && key[e] > bk;
                bk   = take ? key[e] : bk;
                best = take ? e : best;
            }
            used |= 1u << best;
            pref |= ((u64)best) << (4 * i);
        }
        g_prefs[t] = pref;
    }
}

// =====================================================================
// Kernel 2: phased balanced assignment v3.
// choices as bytes in smem; warp e owns expert e's saturation search
// via segmented word scans (__vcmpeq4), no u64 shuffles in phase loop.
// =====================================================================
#define S_PREF_OFF 0
#define S_CH_OFF   (NT * 8)
#define S_W_OFF    (NT * 8 + NT)
#define S_INT_OFF  (NT * 8 + NT + 32 * 4 * 8)
#define SMEM_BYTES (NT * 8 + NT + 32 * 4 * 8 + 128)
// s_int: [0..15] need per expert, [16] active, [17] start, [18] cut, [19] estar

__global__ void __launch_bounds__(1024) assign_kernel(float* __restrict__ out) {
    extern __shared__ unsigned char smem[];
    u64*      s_pref = (u64*)(smem + S_PREF_OFF);
    unsigned* s_ch   = (unsigned*)(smem + S_CH_OFF);       // 2048 words
    u64 (*s_w)[4]    = (u64(*)[4])(smem + S_W_OFF);
    int*      s_int  = (int*)(smem + S_INT_OFF);

    const int tid  = threadIdx.x;
    const int lane = tid & 31;
    const int wid  = tid >> 5;
    const unsigned ltm = (1u << lane) - 1u;

    for (int i = tid; i < NT; i += 1024) s_pref[i] = g_prefs[i];
    if (tid < NE) s_int[tid] = CAP;
    if (tid == 0) { s_int[16] = 0xFFFF; s_int[17] = 0; s_int[18] = 0x7FFFFFFF; s_int[19] = -1; }
    __syncthreads();

    for (int phase = 0; phase <= NE; ++phase) {
        const int s = s_int[17];
        if (s >= NT) break;
        const int active = s_int[16];
        const int estar  = s_int[19];

        // 1. choice update (phase 0: all; later: only estar-choosers)
#pragma unroll
        for (int i = 0; i < 8; ++i) {
            const int t = tid + i * 1024;
            if (t >= s) {
                const int c_old = (int)((s_ch[t >> 2] >> ((t & 3) * 8)) & 0xFFu);
                if (estar < 0 || c_old == estar) {
                    u64 p = s_pref[t];
                    int c = (int)(p & 15);
                    while (!((active >> c) & 1)) { p >>= 4; c = (int)(p & 15); }
                    ((unsigned char*)s_ch)[t] = (unsigned char)c;
                }
            }
        }
        __syncthreads();

        // 2. warp e: find expert e's saturation position (if any)
        if (wid < NE && ((active >> wid) & 1)) {
            const int e = wid;
            const unsigned splat = (unsigned)e * 0x01010101u;
            const int w0 = s >> 2;
            const unsigned m0 = 0xFFFFFFFFu << ((s & 3) * 8);
            const int n   = 2048 - w0;
            const int seg = (n + 31) >> 5;
            const int beg = w0 + lane * seg;
            const int end = min(beg + seg, 2048);
            int off = (lane * 7) % seg;           // bank-spread start
            int cnt = 0;
            for (int k = 0; k < seg; ++k) {
                const int kk = beg + off;
                off = (off + 1 == seg) ? 0 : off + 1;
                if (kk < end) {
                    unsigned cm = __vcmpeq4(s_ch[kk], splat);
                    if (kk == w0) cm &= m0;
                    cnt += __popc(cm) >> 3;
                }
            }
            int inc = cnt;
#pragma unroll
            for (int o = 1; o < 32; o <<= 1) {
                const int u = __shfl_up_sync(FULLM, inc, o);
                if (lane >= o) inc += u;
            }
            const int excl  = inc - cnt;
            const int total = __shfl_sync(FULLM, inc, 31);
            const int need  = s_int[e];
            if (total >= need && excl < need && need <= inc) {
                int rem = need - excl;      // crossing lane: ordered rescan
                int pos = 0;
                for (int w = beg; w < end; ++w) {
                    unsigned cm = __vcmpeq4(s_ch[w], splat);
                    if (w == w0) cm &= m0;
                    const int c = __popc(cm) >> 3;
                    if (c >= rem) {
#pragma unroll
                        for (int bb = 0; bb < 4; ++bb) {
                            if ((cm >> (bb * 8)) & 1u) {
                                if (--rem == 0) { pos = w * 4 + bb; break; }
                            }
                        }
                        break;
                    }
                    rem -= c;
                }
                atomicMin(&s_int[18], (pos << 4) | e);
            }
        }
        __syncthreads();
        const int mv = s_int[18];
        __syncthreads();                      // all read mv before reset

        if (mv == 0x7FFFFFFF) {               // safety
            if (tid == 0) s_int[17] = NT;
            __syncthreads();
            continue;
        }
        const int pstar = mv >> 4, es = mv & 15;

        // 3. need update: warp e counts expert e in [s, pstar]
        if (wid < NE && ((active >> wid) & 1)) {
            const int e = wid;
            const unsigned splat = (unsigned)e * 0x01010101u;
            const int w0 = s >> 2, w1 = pstar >> 2;
            const unsigned m0 = 0xFFFFFFFFu << ((s & 3) * 8);
            const unsigned m1 = 0xFFFFFFFFu >> ((3 - (pstar & 3)) * 8);
            int cnt = 0;
            for (int w = w0 + lane; w <= w1; w += 32) {
                unsigned cm = __vcmpeq4(s_ch[w], splat);
                if (w == w0) cm &= m0;
                if (w == w1) cm &= m1;
                cnt += __popc(cm) >> 3;
            }
#pragma unroll
            for (int o = 16; o; o >>= 1) cnt += __shfl_xor_sync(FULLM, cnt, o);
            if (lane == 0) s_int[e] -= cnt;
        }
        if (tid == 0) {
            s_int[16] = active & ~(1 << es);
            s_int[17] = pstar + 1;
            s_int[18] = 0x7FFFFFFF;
            s_int[19] = es;
        }
        __syncthreads();
    }

    // ---------------- stable counting sort + gather ----------------
    {
        const int base = wid * 256;
        int myE[8];
#pragma unroll
        for (int j = 0; j < 8; ++j) {
            const int t = base + j * 32 + lane;
            myE[j] = (int)((s_ch[t >> 2] >> ((t & 3) * 8)) & 0xFFu);
        }

        u64 c0 = 0, c1 = 0, c2 = 0, c3 = 0;
#pragma unroll
        for (int j = 0; j < 8; ++j) {
            const int c = myE[j];
            const u64 inc = 1ull << ((c & 3) << 4);
            if      ((c >> 2) == 0) c0 += inc;
            else if ((c >> 2) == 1) c1 += inc;
            else if ((c >> 2) == 2) c2 += inc;
            else                    c3 += inc;
        }
#pragma unroll
        for (int o = 16; o; o >>= 1) {
            c0 += __shfl_xor_sync(FULLM, c0, o);
            c1 += __shfl_xor_sync(FULLM, c1, o);
            c2 += __shfl_xor_sync(FULLM, c2, o);
            c3 += __shfl_xor_sync(FULLM, c3, o);
        }
        if (lane == 0) { s_w[wid][0] = c0; s_w[wid][1] = c1; s_w[wid][2] = c2; s_w[wid][3] = c3; }
        __syncthreads();
        if (wid == 0) {
            u64 v0 = s_w[lane][0], v1 = s_w[lane][1], v2 = s_w[lane][2], v3 = s_w[lane][3];
            u64 i0 = v0, i1 = v1, i2 = v2, i3 = v3;
#pragma unroll
            for (int o = 1; o < 32; o <<= 1) {
                u64 u0 = __shfl_up_sync(FULLM, i0, o), u1 = __shfl_up_sync(FULLM, i1, o);
                u64 u2 = __shfl_up_sync(FULLM, i2, o), u3 = __shfl_up_sync(FULLM, i3, o);
                if (lane >= o) { i0 += u0; i1 += u1; i2 += u2; i3 += u3; }
            }
            s_w[lane][0] = i0 - v0; s_w[lane][1] = i1 - v1;
            s_w[lane][2] = i2 - v2; s_w[lane][3] = i3 - v3;
        }
        __syncthreads();
        const u64 p0 = s_w[wid][0], p1 = s_w[wid][1], p2 = s_w[wid][2], p3 = s_w[wid][3];

        u64 r0 = 0, r1 = 0, r2 = 0, r3 = 0;   // counts over earlier j within warp
#pragma unroll
        for (int j = 0; j < 8; ++j) {
            const int e0 = myE[j];
            int rank = 0;
#pragma unroll
            for (int e = 0; e < NE; ++e) {
                const unsigned bal = __ballot_sync(FULLM, e0 == e);
                if (e0 == e) {
                    const u64 pw = (e >> 2) == 0 ? p0 : (e >> 2) == 1 ? p1
                                 : (e >> 2) == 2 ? p2 : p3;
                    const u64 rw = (e >> 2) == 0 ? r0 : (e >> 2) == 1 ? r1
                                 : (e >> 2) == 2 ? r2 : r3;
                    rank = (int)((pw >> ((e & 3) << 4)) & 0xFFFF)
                         + (int)((rw >> ((e & 3) << 4)) & 0xFFFF)
                         + __popc(bal & ltm);
                }
                const u64 inc = (u64)__popc(bal) << ((e & 3) << 4);
                if      ((e >> 2) == 0) r0 += inc;
                else if ((e >> 2) == 1) r1 += inc;
                else if ((e >> 2) == 2) r2 += inc;
                else                    r3 += inc;
            }
            const int t = base + j * 32 + lane;
            out[e0 * CAP + rank] = (float)t;
            out[NT + t] = g_probs[t * NE + e0];
        }
    }
}

// =====================================================================
extern "C" void kernel_launch(void* const* d_in, const int* in_sizes, int n_in,
                              void* d_out, int out_size) {
    const float* f = (const float*)d_in[0];   // features [8192, 2048] f32
    const float* W = (const float*)d_in[1];   // gate weight [16, 2048] f32
    const float* b = (const float*)d_in[2];   // bias [16] f32
    float* out = (float*)d_out;               // [8192] sort_by_expert ++ [8192] gathered

    gemv_kernel<<<NT / 16, 128>>>(f, W, b);

    cudaFuncSetAttribute(assign_kernel,
                         cudaFuncAttributeMaxDynamicSharedMemorySize, SMEM_BYTES);
    assign_kernel<<<1, 1024, SMEM_BYTES>>>(out);
}

// round 5
// speedup vs baseline: 2.7173x; 1.1247x over previous
#include <cuda_runtime.h>

#define NT 8192
#define ND 2048
#define NE 16
#define CAP 512
#define FULLM 0xFFFFFFFFu

typedef unsigned long long u64;

__device__ float g_probs[NT * NE];   // softmax probs per token
__device__ u64   g_prefs[NT];        // packed expert-preference order (16 nibbles)

__device__ __forceinline__ u64 ffma2(u64 a, u64 b, u64 c) {
    u64 d;
    asm("fma.rn.f32x2 %0, %1, %2, %3;" : "=l"(d) : "l"(a), "l"(b), "l"(c));
    return d;
}

// =====================================================================
// Kernel 1: GEMV + softmax + preference packing (unchanged)
// =====================================================================
__global__ void __launch_bounds__(128) gemv_kernel(const float* __restrict__ f,
                                                   const float* __restrict__ W,
                                                   const float* __restrict__ b) {
    const int lane = threadIdx.x & 31;
    const int wid  = threadIdx.x >> 5;
    const int t0   = (blockIdx.x * 4 + wid) * 4;

    const ulonglong2* F  = reinterpret_cast<const ulonglong2*>(f + (size_t)t0 * ND);
    const ulonglong2* Wv = reinterpret_cast<const ulonglong2*>(W);

    u64 acc[4][NE];
#pragma unroll
    for (int t = 0; t < 4; ++t)
#pragma unroll
        for (int e = 0; e < NE; ++e) acc[t][e] = 0ull;

#pragma unroll 2
    for (int i = 0; i < 16; ++i) {
        const int k = i * 32 + lane;
        const ulonglong2 a0 = F[k];
        const ulonglong2 a1 = F[k + 512];
        const ulonglong2 a2 = F[k + 1024];
        const ulonglong2 a3 = F[k + 1536];
#pragma unroll
        for (int e = 0; e < NE; ++e) {
            const ulonglong2 w = Wv[e * 512 + k];
            acc[0][e] = ffma2(a0.x, w.x, acc[0][e]);
            acc[0][e] = ffma2(a0.y, w.y, acc[0][e]);
            acc[1][e] = ffma2(a1.x, w.x, acc[1][e]);
            acc[1][e] = ffma2(a1.y, w.y, acc[1][e]);
            acc[2][e] = ffma2(a2.x, w.x, acc[2][e]);
            acc[2][e] = ffma2(a2.y, w.y, acc[2][e]);
            acc[3][e] = ffma2(a3.x, w.x, acc[3][e]);
            acc[3][e] = ffma2(a3.y, w.y, acc[3][e]);
        }
    }

    float aff[NE];
#pragma unroll
    for (int t = 0; t < 4; ++t) {
#pragma unroll
        for (int e = 0; e < NE; ++e) {
            float sv = __uint_as_float((unsigned)acc[t][e]) +
                       __uint_as_float((unsigned)(acc[t][e] >> 32));
#pragma unroll
            for (int o = 16; o; o >>= 1) sv += __shfl_xor_sync(FULLM, sv, o);
            if (lane == t) aff[e] = sv;
        }
    }

    if (lane < 4) {
        const int t = t0 + lane;
#pragma unroll
        for (int e = 0; e < NE; ++e) aff[e] += __ldg(b + e);

        float m = aff[0];
#pragma unroll
        for (int e = 1; e < NE; ++e) m = fmaxf(m, aff[e]);
        float p[NE]; float s = 0.f;
#pragma unroll
        for (int e = 0; e < NE; ++e) { p[e] = expf(aff[e] - m); s += p[e]; }
        const float inv = 1.f / s;
#pragma unroll
        for (int e = 0; e < NE; ++e) g_probs[t * NE + e] = p[e] * inv;

        u64 key[NE];
#pragma unroll
        for (int e = 0; e < NE; ++e) {
            unsigned u = __float_as_uint(aff[e]);
            u = (u & 0x80000000u) ? ~u : (u | 0x80000000u);
            key[e] = (1ull << 40) | ((u64)u << 4) | (u64)(NE - 1 - e);
        }
        unsigned used = 0;
        u64 pref = 0;
#pragma unroll
        for (int i = 0; i < NE; ++i) {
            int best = 0; u64 bk = 0;
#pragma unroll
            for (int e = 0; e < NE; ++e) {
                const bool take = !((used >> e) & 1u) && key[e] > bk;
                bk   = take ? key[e] : bk;
                best = take ? e : best;
            }
            used |= 1u << best;
            pref |= ((u64)best) << (4 * i);
        }
        g_prefs[t] = pref;
    }
}

// =====================================================================
// Kernel 2: phased balanced assignment v4 — hierarchical block counts.
// s_blk[e][k] = #tokens in block k (256 tokens) currently choosing e,
// maintained incrementally; saturation search touches ~160 words/expert
// instead of ~2048.
// =====================================================================
#define S_PREF_OFF 0
#define S_CH_OFF   65536
#define S_BLK_OFF  73728
#define S_W_OFF    75776
#define S_INT_OFF  76800
#define SMEM_BYTES 76928
// s_int: [0..15] need, [16] active, [17] start, [18] cut, [19] estar

__global__ void __launch_bounds__(1024) assign_kernel(float* __restrict__ out) {
    extern __shared__ unsigned char smem[];
    u64*      s_pref = (u64*)(smem + S_PREF_OFF);
    unsigned* s_ch   = (unsigned*)(smem + S_CH_OFF);   // 2048 words (bytes = choices)
    int*      s_blk  = (int*)(smem + S_BLK_OFF);       // [16][32]
    u64 (*s_w)[4]    = (u64(*)[4])(smem + S_W_OFF);
    int*      s_int  = (int*)(smem + S_INT_OFF);

    const int tid  = threadIdx.x;
    const int lane = tid & 31;
    const int wid  = tid >> 5;
    const unsigned ltm = (1u << lane) - 1u;

    for (int i = tid; i < NT; i += 1024) s_pref[i] = g_prefs[i];
    if (tid < NE * 32) s_blk[tid] = 0;
    if (tid < NE) s_int[tid] = CAP;
    if (tid == 0) { s_int[16] = 0xFFFF; s_int[17] = 0; s_int[18] = 0x7FFFFFFF; s_int[19] = -1; }
    __syncthreads();

    for (int phase = 0; phase <= NE; ++phase) {
        const int s = s_int[17];
        if (s >= NT) break;
        const int active = s_int[16];
        const int estar  = s_int[19];

        // ---- step 1: (re)derive choices; maintain block counts ----
        if (estar < 0) {
#pragma unroll
            for (int i = 0; i < 8; ++i) {
                const int t = tid + i * 1024;
                const int c = (int)(s_pref[t] & 15);   // all experts active
                ((unsigned char*)s_ch)[t] = (unsigned char)c;
                atomicAdd(&s_blk[c * 32 + (t >> 8)], 1);
            }
        } else {
#pragma unroll
            for (int i = 0; i < 8; ++i) {
                const int t = tid + i * 1024;
                if (t >= s &&
                    (int)((s_ch[t >> 2] >> ((t & 3) * 8)) & 0xFFu) == estar) {
                    u64 p = s_pref[t];
                    int c = (int)(p & 15);
                    while (!((active >> c) & 1)) { p >>= 4; c = (int)(p & 15); }
                    ((unsigned char*)s_ch)[t] = (unsigned char)c;
                    atomicAdd(&s_blk[c * 32 + (t >> 8)], 1);
                    atomicAdd(&s_blk[estar * 32 + (t >> 8)], -1);
                }
            }
        }
        __syncthreads();

        // ---- step 2: warp e finds expert e's saturation position ----
        if (wid < NE && ((active >> wid) & 1)) {
            const int e = wid;
            const unsigned splat = (unsigned)e * 0x01010101u;
            const int need = s_int[e];
            const int pb   = s >> 8;             // partial block index
            const int ws   = s >> 2;             // first live word
            const int we_  = (pb + 1) * 64;      // end word of partial block
            const unsigned mfirst = 0xFFFFFFFFu << ((s & 3) * 8);

            // partial block: lane owns 2 contiguous words
            const int i0 = ws + lane * 2;
            unsigned cm0 = 0, cm1 = 0;
            if (i0 < we_) {
                cm0 = __vcmpeq4(s_ch[i0], splat);
                if (i0 == ws) cm0 &= mfirst;
            }
            if (i0 + 1 < we_) cm1 = __vcmpeq4(s_ch[i0 + 1], splat);
            const int lcnt = (__popc(cm0) + __popc(cm1)) >> 3;
            int linc = lcnt;
#pragma unroll
            for (int o = 1; o < 32; o <<= 1) {
                const int u = __shfl_up_sync(FULLM, linc, o);
                if (lane >= o) linc += u;
            }
            const int ptotal = __shfl_sync(FULLM, linc, 31);

            // block counts beyond the partial block
            const int bval = (lane > pb) ? s_blk[e * 32 + lane] : 0;
            int binc = bval;
#pragma unroll
            for (int o = 1; o < 32; o <<= 1) {
                const int u = __shfl_up_sync(FULLM, binc, o);
                if (lane >= o) binc += u;
            }
            const int btotal = __shfl_sync(FULLM, binc, 31);

            if (ptotal + btotal >= need) {
                if (ptotal >= need) {
                    // crossing inside the partial block
                    const unsigned bal = __ballot_sync(FULLM, linc >= need);
                    const int cl = __ffs(bal) - 1;
                    if (lane == cl) {
                        int rem = need - (linc - lcnt);
                        int pos = -1;
#pragma unroll
                        for (int bb = 0; bb < 4 && pos < 0; ++bb)
                            if ((cm0 >> (bb * 8)) & 1u && --rem == 0) pos = i0 * 4 + bb;
#pragma unroll
                        for (int bb = 0; bb < 4 && pos < 0; ++bb)
                            if ((cm1 >> (bb * 8)) & 1u && --rem == 0) pos = (i0 + 1) * 4 + bb;
                        atomicMin(&s_int[18], (pos << 4) | e);
                    }
                } else {
                    const int rem2 = need - ptotal;
                    const unsigned bal = __ballot_sync(FULLM, binc >= rem2);
                    const int kc   = __ffs(bal) - 1;            // crossing block
                    const int excl = __shfl_sync(FULLM, binc - bval, kc);
                    const int rem3 = rem2 - excl;
                    // scan crossing block (fully live: kc > pb)
                    const int j0 = kc * 64 + lane * 2;
                    const unsigned d0 = __vcmpeq4(s_ch[j0], splat);
                    const unsigned d1 = __vcmpeq4(s_ch[j0 + 1], splat);
                    const int lc = (__popc(d0) + __popc(d1)) >> 3;
                    int li = lc;
#pragma unroll
                    for (int o = 1; o < 32; o <<= 1) {
                        const int u = __shfl_up_sync(FULLM, li, o);
                        if (lane >= o) li += u;
                    }
                    const unsigned bal2 = __ballot_sync(FULLM, li >= rem3);
                    const int cl2 = __ffs(bal2) - 1;
                    if (lane == cl2) {
                        int rem = rem3 - (li - lc);
                        int pos = -1;
#pragma unroll
                        for (int bb = 0; bb < 4 && pos < 0; ++bb)
                            if ((d0 >> (bb * 8)) & 1u && --rem == 0) pos = j0 * 4 + bb;
#pragma unroll
                        for (int bb = 0; bb < 4 && pos < 0; ++bb)
                            if ((d1 >> (bb * 8)) & 1u && --rem == 0) pos = (j0 + 1) * 4 + bb;
                        atomicMin(&s_int[18], (pos << 4) | e);
                    }
                }
            }
        }
        __syncthreads();
        const int mv = s_int[18];
        __syncthreads();

        if (mv == 0x7FFFFFFF) {                  // safety; unreachable
            if (tid == 0) s_int[17] = NT;
            __syncthreads();
            continue;
        }
        const int pstar = mv >> 4, es = mv & 15;

        // ---- step 3: warp e subtracts its finalized count in [s, pstar] ----
        if (wid < NE && ((active >> wid) & 1)) {
            const int e = wid;
            const unsigned splat = (unsigned)e * 0x01010101u;
            const int w0 = s >> 2, w1 = pstar >> 2;
            const unsigned m0 = 0xFFFFFFFFu << ((s & 3) * 8);
            const unsigned m1 = 0xFFFFFFFFu >> ((3 - (pstar & 3)) * 8);
            int cnt = 0;
            for (int w = w0 + lane; w <= w1; w += 32) {
                unsigned cm = __vcmpeq4(s_ch[w], splat);
                if (w == w0) cm &= m0;
                if (w == w1) cm &= m1;
                cnt += __popc(cm) >> 3;
            }
#pragma unroll
            for (int o = 16; o; o >>= 1) cnt += __shfl_xor_sync(FULLM, cnt, o);
            if (lane == 0) s_int[e] -= cnt;
        }
        if (tid == 0) {
            s_int[16] = active & ~(1 << es);
            s_int[17] = pstar + 1;
            s_int[18] = 0x7FFFFFFF;
            s_int[19] = es;
        }
        __syncthreads();
    }

    // ---------------- stable counting sort + gather ----------------
    {
        const int base = wid * 256;
        int myE[8];
#pragma unroll
        for (int j = 0; j < 8; ++j) {
            const int t = base + j * 32 + lane;
            myE[j] = (int)((s_ch[t >> 2] >> ((t & 3) * 8)) & 0xFFu);
        }

        u64 c0 = 0, c1 = 0, c2 = 0, c3 = 0;
#pragma unroll
        for (int j = 0; j < 8; ++j) {
            const int c = myE[j];
            const u64 inc = 1ull << ((c & 3) << 4);
            if      ((c >> 2) == 0) c0 += inc;
            else if ((c >> 2) == 1) c1 += inc;
            else if ((c >> 2) == 2) c2 += inc;
            else                    c3 += inc;
        }
#pragma unroll
        for (int o = 16; o; o >>= 1) {
            c0 += __shfl_xor_sync(FULLM, c0, o);
            c1 += __shfl_xor_sync(FULLM, c1, o);
            c2 += __shfl_xor_sync(FULLM, c2, o);
            c3 += __shfl_xor_sync(FULLM, c3, o);
        }
        if (lane == 0) { s_w[wid][0] = c0; s_w[wid][1] = c1; s_w[wid][2] = c2; s_w[wid][3] = c3; }
        __syncthreads();
        if (wid == 0) {
            u64 v0 = s_w[lane][0], v1 = s_w[lane][1], v2 = s_w[lane][2], v3 = s_w[lane][3];
            u64 i0 = v0, i1 = v1, i2 = v2, i3 = v3;
#pragma unroll
            for (int o = 1; o < 32; o <<= 1) {
                u64 u0 = __shfl_up_sync(FULLM, i0, o), u1 = __shfl_up_sync(FULLM, i1, o);
                u64 u2 = __shfl_up_sync(FULLM, i2, o), u3 = __shfl_up_sync(FULLM, i3, o);
                if (lane >= o) { i0 += u0; i1 += u1; i2 += u2; i3 += u3; }
            }
            s_w[lane][0] = i0 - v0; s_w[lane][1] = i1 - v1;
            s_w[lane][2] = i2 - v2; s_w[lane][3] = i3 - v3;
        }
        __syncthreads();
        const u64 p0 = s_w[wid][0], p1 = s_w[wid][1], p2 = s_w[wid][2], p3 = s_w[wid][3];

        u64 r0 = 0, r1 = 0, r2 = 0, r3 = 0;
#pragma unroll
        for (int j = 0; j < 8; ++j) {
            const int e0 = myE[j];
            int rank = 0;
#pragma unroll
            for (int e = 0; e < NE; ++e) {
                const unsigned bal = __ballot_sync(FULLM, e0 == e);
                if (e0 == e) {
                    const u64 pw = (e >> 2) == 0 ? p0 : (e >> 2) == 1 ? p1
                                 : (e >> 2) == 2 ? p2 : p3;
                    const u64 rw = (e >> 2) == 0 ? r0 : (e >> 2) == 1 ? r1
                                 : (e >> 2) == 2 ? r2 : r3;
                    rank = (int)((pw >> ((e & 3) << 4)) & 0xFFFF)
                         + (int)((rw >> ((e & 3) << 4)) & 0xFFFF)
                         + __popc(bal & ltm);
                }
                const u64 inc = (u64)__popc(bal) << ((e & 3) << 4);
                if      ((e >> 2) == 0) r0 += inc;
                else if ((e >> 2) == 1) r1 += inc;
                else if ((e >> 2) == 2) r2 += inc;
                else                    r3 += inc;
            }
            const int t = base + j * 32 + lane;
            out[e0 * CAP + rank] = (float)t;
            out[NT + t] = g_probs[t * NE + e0];
        }
    }
}

// =====================================================================
extern "C" void kernel_launch(void* const* d_in, const int* in_sizes, int n_in,
                              void* d_out, int out_size) {
    const float* f = (const float*)d_in[0];   // features [8192, 2048] f32
    const float* W = (const float*)d_in[1];   // gate weight [16, 2048] f32
    const float* b = (const float*)d_in[2];   // bias [16] f32
    float* out = (float*)d_out;               // [8192] sort_by_expert ++ [8192] gathered

    gemv_kernel<<<NT / 16, 128>>>(f, W, b);

    cudaFuncSetAttribute(assign_kernel,
                         cudaFuncAttributeMaxDynamicSharedMemorySize, SMEM_BYTES);
    assign_kernel<<<1, 1024, SMEM_BYTES>>>(out);
}